// round 7
// baseline (speedup 1.0000x reference)
#include <cuda_runtime.h>
#include <cuda_bf16.h>
#include <cstdint>

// B=16,H=128 -> 2048 groups; per group X[128,256], D=32.
#define NTHR 512

// ---------------- SMEM layout (bytes) ----------------
#define XSTR    544                  // X row stride
#define XH_OFF  0                    // X hi [128][XSTR] = 69,632
#define XL_OFF  69632                // X lo
#define WB      139264               // single weight buffer (34,816)
#define WCHUNK  34816
#define WLO     17408
#define WK2     174080               // Wk staging during proj (34,816; later reused)
#define QH_OFF  174080               // Q image hi [128][96]  (overlays WK2, post-proj)
#define ILO     12288                // hi->lo delta for Q/K images
#define KH_OFF  198656               // K image hi [128][96]
#define ISTR    96
#define VTH_OFF 174080               // V^T chunk hi [32][288] (overlays Q image, post-scores)
#define VTL_D   9216                 // VT hi->lo delta
#define VSTR    288
#define RED_OFF 192512               // 16KB partial-sum exchange (post-scores)
#define RMAX_OFF 223232              // [128][2] f32
#define RSUM_OFF 224256              // [128][2] f32
#define SMEM_BYTES 225280

// k-permutation: (2q,2q+1,2q+8,2q+9) contiguous per 16-block -> LDS.64 frags
__device__ __forceinline__ int kslot(int k) {
    return (k & ~15) | (((k >> 1) & 3) << 2) | (((k >> 3) & 1) << 1) | (k & 1);
}

// 10 weight-chunk images: 0=Wq, 1=Wk, 2..9=Wv col-chunks of 32
__device__ __align__(16) unsigned char g_wimg[10 * WCHUNK];

__device__ __forceinline__ uint32_t smem_u32(const void* p) {
    uint32_t a;
    asm("{ .reg .u64 t; cvta.to.shared.u64 t, %1; cvt.u32.u64 %0, t; }" : "=r"(a) : "l"(p));
    return a;
}
__device__ __forceinline__ void cp16(void* sdst, const void* gsrc) {
    asm volatile("cp.async.cg.shared.global [%0], [%1], 16;"
                 :: "r"(smem_u32(sdst)), "l"(gsrc));
}
#define CP_COMMIT() asm volatile("cp.async.commit_group;" ::: "memory")
#define CP_WAIT0()  asm volatile("cp.async.wait_group 0;" ::: "memory")

__device__ __forceinline__ void mma16816(float* c, uint32_t a0, uint32_t a1,
                                         uint32_t a2, uint32_t a3,
                                         uint32_t b0, uint32_t b1) {
    asm volatile(
        "mma.sync.aligned.m16n8k16.row.col.f32.bf16.bf16.f32 "
        "{%0,%1,%2,%3},{%4,%5,%6,%7},{%8,%9},{%0,%1,%2,%3};"
        : "+f"(c[0]), "+f"(c[1]), "+f"(c[2]), "+f"(c[3])
        : "r"(a0), "r"(a1), "r"(a2), "r"(a3), "r"(b0), "r"(b1));
}
__device__ __forceinline__ void mma3(float* c, uint2 ah0, uint2 ah1,
                                     uint2 al0, uint2 al1, uint2 bh, uint2 bl) {
    mma16816(c, ah0.x, ah1.x, ah0.y, ah1.y, bh.x, bh.y);
    mma16816(c, ah0.x, ah1.x, ah0.y, ah1.y, bl.x, bl.y);
    mma16816(c, al0.x, al1.x, al0.y, al1.y, bh.x, bh.y);
}
__device__ __forceinline__ uint32_t pack_hi(float x, float y) {
    __nv_bfloat162 p = __floats2bfloat162_rn(x, y);
    return *reinterpret_cast<uint32_t*>(&p);
}
__device__ __forceinline__ uint32_t pack_lo(float x, float y) {
    float xh = __bfloat162float(__float2bfloat16(x));
    float yh = __bfloat162float(__float2bfloat16(y));
    __nv_bfloat162 p = __floats2bfloat162_rn(x - xh, y - yh);
    return *reinterpret_cast<uint32_t*>(&p);
}

// =============== prep: weights -> bf16 hi/lo SMEM-image chunks ===============
__global__ void prep_weights(const float* __restrict__ Wq, const float* __restrict__ Wk,
                             const float* __restrict__ Wv) {
    int idx = blockIdx.x * 256 + threadIdx.x;   // 81920 total
    int chunk = idx >> 13;
    int n = (idx >> 8) & 31;
    int k = idx & 255;
    float w;
    if (chunk == 0)      w = Wq[k * 32 + n];
    else if (chunk == 1) w = Wk[k * 32 + n];
    else                 w = Wv[k * 256 + (chunk - 2) * 32 + n];
    __nv_bfloat16 hh = __float2bfloat16(w);
    __nv_bfloat16 ll = __float2bfloat16(w - __bfloat162float(hh));
    unsigned off = (unsigned)chunk * WCHUNK + (unsigned)n * XSTR + (unsigned)kslot(k) * 2;
    *(__nv_bfloat16*)(g_wimg + off)       = hh;
    *(__nv_bfloat16*)(g_wimg + off + WLO) = ll;
}

// VT transpose-store: warp's 16 cols (16h + nt2*8 + 2q + odd) x 16 tokens
__device__ __forceinline__ void store_vt(unsigned char* sm, const float Cv[2][4],
                                         int h, int q, bool oddlq, int pA, int pB) {
    #pragma unroll
    for (int nt2 = 0; nt2 < 2; nt2++) {
        float v0 = Cv[nt2][0], v1 = Cv[nt2][1], v2 = Cv[nt2][2], v3 = Cv[nt2][3];
        float sendA = oddlq ? v0 : v1;
        float recvA = __shfl_xor_sync(0xffffffffu, sendA, 4);
        float sendB = oddlq ? v2 : v3;
        float recvB = __shfl_xor_sync(0xffffffffu, sendB, 4);
        float a0 = oddlq ? recvA : v0, a1 = oddlq ? v1 : recvA;
        float b0 = oddlq ? recvB : v2, b1 = oddlq ? v3 : recvB;
        unsigned cc = (unsigned)(16 * h + nt2 * 8 + 2 * q + (oddlq ? 1 : 0)) * VSTR;
        *(uint32_t*)(sm + VTH_OFF + cc + pA)         = pack_hi(a0, a1);
        *(uint32_t*)(sm + VTH_OFF + cc + pB)         = pack_hi(b0, b1);
        *(uint32_t*)(sm + VTH_OFF + VTL_D + cc + pA) = pack_lo(a0, a1);
        *(uint32_t*)(sm + VTH_OFF + VTL_D + cc + pB) = pack_lo(b0, b1);
    }
}

// =============== main: one CTA (16 warps) per (b,h) group ===============
__global__ __launch_bounds__(NTHR, 1)
void attn_mma_kernel(const float* __restrict__ X,
                     const float* __restrict__ bq, const float* __restrict__ bk,
                     const float* __restrict__ bv, float* __restrict__ out) {
    extern __shared__ unsigned char sm[];
    const int t = threadIdx.x, w = t >> 5, lane = t & 31;
    const int q = lane & 3, lq = lane >> 2;
    const int rb = w >> 1, h = w & 1;          // row-block, n/k-half
    const int R = rb * 16;
    const long long g = blockIdx.x;
    const float* Xg = X + g * 32768LL;
    float* Og = out + g * 32768LL;

    // stage Wq -> WB, Wk -> WK2
    for (int i = t; i < WCHUNK / 16; i += NTHR) cp16(sm + WB + i * 16, g_wimg + i * 16);
    for (int i = t; i < WCHUNK / 16; i += NTHR) cp16(sm + WK2 + i * 16, g_wimg + WCHUNK + i * 16);
    CP_COMMIT();

    // X load + bf16 hi/lo split into permuted layout
    {
        const float4* X4 = (const float4*)Xg;
        #pragma unroll
        for (int it = 0; it < 16; it++) {
            int i = it * NTHR + t;
            int row = i >> 6, k0 = (i & 63) * 4;
            float4 f = X4[i];
            int s0 = kslot(k0), s1 = kslot(k0 + 2);
            unsigned b = (unsigned)row * XSTR;
            *(uint32_t*)(sm + XH_OFF + b + s0 * 2) = pack_hi(f.x, f.y);
            *(uint32_t*)(sm + XH_OFF + b + s1 * 2) = pack_hi(f.z, f.w);
            *(uint32_t*)(sm + XL_OFF + b + s0 * 2) = pack_lo(f.x, f.y);
            *(uint32_t*)(sm + XL_OFF + b + s1 * 2) = pack_lo(f.z, f.w);
        }
    }
    CP_WAIT0();
    __syncthreads();

    const unsigned char* XH0 = sm + XH_OFF + (unsigned)(R + lq) * XSTR;
    const unsigned char* XH1 = XH0 + 8 * XSTR;
    const unsigned char* XL0 = sm + XL_OFF + (unsigned)(R + lq) * XSTR;
    const unsigned char* XL1 = XL0 + 8 * XSTR;

    // ---- projection: even warps Q (WB), odd warps K (WK2), rows R..R+15 ----
    {
        const unsigned wsrc = h ? WK2 : WB;
        float Cp[4][4];
        #pragma unroll
        for (int n = 0; n < 4; n++) { Cp[n][0] = Cp[n][1] = Cp[n][2] = Cp[n][3] = 0.f; }
        #pragma unroll 4
        for (int kt = 0; kt < 16; kt++) {
            unsigned ko = kt * 32 + q * 8;
            uint2 ah0 = *(const uint2*)(XH0 + ko), ah1 = *(const uint2*)(XH1 + ko);
            uint2 al0 = *(const uint2*)(XL0 + ko), al1 = *(const uint2*)(XL1 + ko);
            #pragma unroll
            for (int nt = 0; nt < 4; nt++) {
                const unsigned char* B = sm + wsrc + (unsigned)(nt * 8 + lq) * XSTR + ko;
                mma3(Cp[nt], ah0, ah1, al0, al1, *(const uint2*)B, *(const uint2*)(B + WLO));
            }
        }
        __syncthreads();   // all proj reads of WB/WK2 done

        // write Q/K image (+bias), hi/lo, kslot-permuted
        const float* bias = h ? bk : bq;
        const unsigned ih = h ? KH_OFF : QH_OFF;
        #pragma unroll
        for (int nt = 0; nt < 4; nt++) {
            float2 bb = *(const float2*)(bias + nt * 8 + 2 * q);
            float c0 = Cp[nt][0] + bb.x, c1 = Cp[nt][1] + bb.y;
            float c2 = Cp[nt][2] + bb.x, c3 = Cp[nt][3] + bb.y;
            int p = kslot(nt * 8 + 2 * q) * 2;
            unsigned o0 = (unsigned)(R + lq) * ISTR + p;
            unsigned o1 = (unsigned)(R + 8 + lq) * ISTR + p;
            *(uint32_t*)(sm + ih + o0)       = pack_hi(c0, c1);
            *(uint32_t*)(sm + ih + o1)       = pack_hi(c2, c3);
            *(uint32_t*)(sm + ih + ILO + o0) = pack_lo(c0, c1);
            *(uint32_t*)(sm + ih + ILO + o1) = pack_lo(c2, c3);
        }
    }
    // prefetch Wv0 -> WB (proj reads done at sync above)
    for (int i = t; i < WCHUNK / 16; i += NTHR) cp16(sm + WB + i * 16, g_wimg + 2 * WCHUNK + i * 16);
    CP_COMMIT();
    __syncthreads();   // Q/K images visible

    // ---- scores: warp computes its token-half (nt = h*8 + 0..7) ----
    float Cs[8][4];
    {
        uint32_t qh[2][4], ql[2][4];
        #pragma unroll
        for (int kt = 0; kt < 2; kt++) {
            unsigned ko = kt * 32 + q * 8;
            uint2 a0 = *(const uint2*)(sm + QH_OFF + (unsigned)(R + lq) * ISTR + ko);
            uint2 a1 = *(const uint2*)(sm + QH_OFF + (unsigned)(R + 8 + lq) * ISTR + ko);
            qh[kt][0] = a0.x; qh[kt][1] = a1.x; qh[kt][2] = a0.y; qh[kt][3] = a1.y;
            uint2 c0 = *(const uint2*)(sm + QH_OFF + ILO + (unsigned)(R + lq) * ISTR + ko);
            uint2 c1 = *(const uint2*)(sm + QH_OFF + ILO + (unsigned)(R + 8 + lq) * ISTR + ko);
            ql[kt][0] = c0.x; ql[kt][1] = c1.x; ql[kt][2] = c0.y; ql[kt][3] = c1.y;
        }
        #pragma unroll
        for (int n = 0; n < 8; n++) { Cs[n][0] = Cs[n][1] = Cs[n][2] = Cs[n][3] = 0.f; }
        #pragma unroll
        for (int nt = 0; nt < 8; nt++) {
            unsigned krow = (unsigned)((h * 8 + nt) * 8 + lq) * ISTR;
            #pragma unroll
            for (int kt = 0; kt < 2; kt++) {
                unsigned ko = kt * 32 + q * 8;
                uint2 bh = *(const uint2*)(sm + KH_OFF + krow + ko);
                uint2 bl = *(const uint2*)(sm + KH_OFF + ILO + krow + ko);
                mma16816(Cs[nt], qh[kt][0], qh[kt][1], qh[kt][2], qh[kt][3], bh.x, bh.y);
                mma16816(Cs[nt], qh[kt][0], qh[kt][1], qh[kt][2], qh[kt][3], bl.x, bl.y);
                mma16816(Cs[nt], ql[kt][0], ql[kt][1], ql[kt][2], ql[kt][3], bh.x, bh.y);
            }
        }
    }

    // ---- softmax across the two halves via smem row stats ----
    {
        float* RMX = (float*)(sm + RMAX_OFF);
        float* RSM = (float*)(sm + RSUM_OFF);
        float m0 = -1e30f, m1 = -1e30f;
        #pragma unroll
        for (int nt = 0; nt < 8; nt++) {
            m0 = fmaxf(m0, fmaxf(Cs[nt][0], Cs[nt][1]));
            m1 = fmaxf(m1, fmaxf(Cs[nt][2], Cs[nt][3]));
        }
        m0 = fmaxf(m0, __shfl_xor_sync(0xffffffffu, m0, 1));
        m0 = fmaxf(m0, __shfl_xor_sync(0xffffffffu, m0, 2));
        m1 = fmaxf(m1, __shfl_xor_sync(0xffffffffu, m1, 1));
        m1 = fmaxf(m1, __shfl_xor_sync(0xffffffffu, m1, 2));
        if (q == 0) { RMX[(R + lq) * 2 + h] = m0; RMX[(R + 8 + lq) * 2 + h] = m1; }
        __syncthreads();
        m0 = fmaxf(RMX[(R + lq) * 2], RMX[(R + lq) * 2 + 1]);
        m1 = fmaxf(RMX[(R + 8 + lq) * 2], RMX[(R + 8 + lq) * 2 + 1]);
        float s0 = 0.f, s1 = 0.f;
        #pragma unroll
        for (int nt = 0; nt < 8; nt++) {
            Cs[nt][0] = __expf(Cs[nt][0] - m0); Cs[nt][1] = __expf(Cs[nt][1] - m0);
            Cs[nt][2] = __expf(Cs[nt][2] - m1); Cs[nt][3] = __expf(Cs[nt][3] - m1);
            s0 += Cs[nt][0] + Cs[nt][1];
            s1 += Cs[nt][2] + Cs[nt][3];
        }
        s0 += __shfl_xor_sync(0xffffffffu, s0, 1);
        s0 += __shfl_xor_sync(0xffffffffu, s0, 2);
        s1 += __shfl_xor_sync(0xffffffffu, s1, 1);
        s1 += __shfl_xor_sync(0xffffffffu, s1, 2);
        if (q == 0) { RSM[(R + lq) * 2 + h] = s0; RSM[(R + 8 + lq) * 2 + h] = s1; }
        __syncthreads();
        float i0 = 1.f / (RSM[(R + lq) * 2] + RSM[(R + lq) * 2 + 1]);
        float i1 = 1.f / (RSM[(R + 8 + lq) * 2] + RSM[(R + 8 + lq) * 2 + 1]);
        #pragma unroll
        for (int nt = 0; nt < 8; nt++) {
            Cs[nt][0] *= i0; Cs[nt][1] *= i0; Cs[nt][2] *= i1; Cs[nt][3] *= i1;
        }
    }

    // attn A-frags for this warp's 64 tokens (kt' 0..3, global kt = h*4+kt')
    uint32_t ah[4][4], al[4][4];
    #pragma unroll
    for (int kt = 0; kt < 4; kt++) {
        ah[kt][0] = pack_hi(Cs[2*kt][0],   Cs[2*kt][1]);
        ah[kt][1] = pack_hi(Cs[2*kt][2],   Cs[2*kt][3]);
        ah[kt][2] = pack_hi(Cs[2*kt+1][0], Cs[2*kt+1][1]);
        ah[kt][3] = pack_hi(Cs[2*kt+1][2], Cs[2*kt+1][3]);
        al[kt][0] = pack_lo(Cs[2*kt][0],   Cs[2*kt][1]);
        al[kt][1] = pack_lo(Cs[2*kt][2],   Cs[2*kt][3]);
        al[kt][2] = pack_lo(Cs[2*kt+1][0], Cs[2*kt+1][1]);
        al[kt][3] = pack_lo(Cs[2*kt+1][2], Cs[2*kt+1][3]);
    }

    const int j2 = 2 * (lq >> 1);
    const int pA = kslot(R + j2) * 2;
    const int pB = kslot(R + j2 + 8) * 2;
    const bool oddlq = (lq & 1);

    // ---- Vproj(0): warp computes its n-half (nt2 0..1 -> n = 16h+nt2*8+lq) ----
    float Cv[2][4];
    CP_WAIT0();
    #pragma unroll
    for (int n = 0; n < 2; n++) { Cv[n][0] = Cv[n][1] = Cv[n][2] = Cv[n][3] = 0.f; }
    #pragma unroll 4
    for (int kt = 0; kt < 16; kt++) {
        unsigned ko = kt * 32 + q * 8;
        uint2 ah0 = *(const uint2*)(XH0 + ko), ah1 = *(const uint2*)(XH1 + ko);
        uint2 al0 = *(const uint2*)(XL0 + ko), al1 = *(const uint2*)(XL1 + ko);
        #pragma unroll
        for (int nt2 = 0; nt2 < 2; nt2++) {
            const unsigned char* B = sm + WB + (unsigned)(16 * h + nt2 * 8 + lq) * XSTR + ko;
            mma3(Cv[nt2], ah0, ah1, al0, al1, *(const uint2*)B, *(const uint2*)(B + WLO));
        }
    }
    __syncthreads();   // WB reads done; Q image reads (scores) long done
    for (int i = t; i < WCHUNK / 16; i += NTHR) cp16(sm + WB + i * 16, g_wimg + 3 * WCHUNK + i * 16);
    CP_COMMIT();
    store_vt(sm, Cv, h, q, oddlq, pA, pB);
    __syncthreads();   // VT(0) visible

    // ---------------- chunk loop ----------------
    #pragma unroll 1
    for (int c = 0; c < 8; c++) {
        // AV(c): partial O over this warp's 64 tokens
        float Co[4][4];
        #pragma unroll
        for (int n = 0; n < 4; n++) { Co[n][0] = Co[n][1] = Co[n][2] = Co[n][3] = 0.f; }
        #pragma unroll
        for (int kt = 0; kt < 4; kt++) {
            unsigned ko = (unsigned)(h * 4 + kt) * 32 + q * 8;
            #pragma unroll
            for (int nt = 0; nt < 4; nt++) {
                const unsigned char* Vp = sm + VTH_OFF + (unsigned)(nt * 8 + lq) * VSTR + ko;
                uint2 bh = *(const uint2*)Vp;
                uint2 bl = *(const uint2*)(Vp + VTL_D);
                mma16816(Co[nt], ah[kt][0], ah[kt][1], ah[kt][2], ah[kt][3], bh.x, bh.y);
                mma16816(Co[nt], ah[kt][0], ah[kt][1], ah[kt][2], ah[kt][3], bl.x, bl.y);
                mma16816(Co[nt], al[kt][0], al[kt][1], al[kt][2], al[kt][3], bh.x, bh.y);
            }
        }
        // partial exchange: store OTHER-half nt pair to RED
        {
            int nb = h ? 0 : 2;
            #pragma unroll
            for (int i = 0; i < 2; i++) {
                int nt = nb + i;
                float* rp = (float*)(sm + RED_OFF) + (unsigned)(rb * 4 + nt) * 128;
                *(float2*)(rp + lq * 8 + 2 * q)       = make_float2(Co[nt][0], Co[nt][1]);
                *(float2*)(rp + (lq + 8) * 8 + 2 * q) = make_float2(Co[nt][2], Co[nt][3]);
            }
        }
        __syncthreads();
        // finalize OWN-half nt pair: own Co + partner partial + bv -> gmem
        {
            int nb = h ? 2 : 0;
            #pragma unroll
            for (int i = 0; i < 2; i++) {
                int nt = nb + i;
                int col = c * 32 + nt * 8 + 2 * q;
                const float* rp = (const float*)(sm + RED_OFF) + (unsigned)(rb * 4 + nt) * 128;
                float2 p0 = *(const float2*)(rp + lq * 8 + 2 * q);
                float2 p1 = *(const float2*)(rp + (lq + 8) * 8 + 2 * q);
                float2 bb = *(const float2*)(bv + col);
                *(float2*)(Og + (long long)(R + lq) * 256 + col) =
                    make_float2(Co[nt][0] + p0.x + bb.x, Co[nt][1] + p0.y + bb.y);
                *(float2*)(Og + (long long)(R + 8 + lq) * 256 + col) =
                    make_float2(Co[nt][2] + p1.x + bb.x, Co[nt][3] + p1.y + bb.y);
            }
        }
        if (c < 7) {
            CP_WAIT0();   // Wv(c+1) landed
            #pragma unroll
            for (int n = 0; n < 2; n++) { Cv[n][0] = Cv[n][1] = Cv[n][2] = Cv[n][3] = 0.f; }
            #pragma unroll 4
            for (int kt = 0; kt < 16; kt++) {
                unsigned ko = kt * 32 + q * 8;
                uint2 ah0 = *(const uint2*)(XH0 + ko), ah1 = *(const uint2*)(XH1 + ko);
                uint2 al0 = *(const uint2*)(XL0 + ko), al1 = *(const uint2*)(XL1 + ko);
                #pragma unroll
                for (int nt2 = 0; nt2 < 2; nt2++) {
                    const unsigned char* B = sm + WB + (unsigned)(16 * h + nt2 * 8 + lq) * XSTR + ko;
                    mma3(Cv[nt2], ah0, ah1, al0, al1, *(const uint2*)B, *(const uint2*)(B + WLO));
                }
            }
            __syncthreads();   // WB reads + RED reads done
            if (c < 6) {
                for (int i = t; i < WCHUNK / 16; i += NTHR)
                    cp16(sm + WB + i * 16, g_wimg + (unsigned)(4 + c) * WCHUNK + i * 16);
                CP_COMMIT();
            }
            store_vt(sm, Cv, h, q, oddlq, pA, pB);
            __syncthreads();   // VT(c+1) visible
        }
    }
}

extern "C" void kernel_launch(void* const* d_in, const int* in_sizes, int n_in,
                              void* d_out, int out_size) {
    const float* X  = (const float*)d_in[0];
    const float* Wq = (const float*)d_in[1];
    const float* bq = (const float*)d_in[2];
    const float* Wk = (const float*)d_in[3];
    const float* bk = (const float*)d_in[4];
    const float* Wv = (const float*)d_in[5];
    const float* bv = (const float*)d_in[6];
    float* out = (float*)d_out;

    const int groups = in_sizes[0] / (128 * 256);   // 2048

    prep_weights<<<320, 256>>>(Wq, Wk, Wv);

    cudaFuncSetAttribute(attn_mma_kernel,
                         cudaFuncAttributeMaxDynamicSharedMemorySize, SMEM_BYTES);
    attn_mma_kernel<<<groups, NTHR, SMEM_BYTES>>>(X, bq, bk, bv, out);
}

// round 8
// speedup vs baseline: 1.0121x; 1.0121x over previous
#include <cuda_runtime.h>
#include <cuda_bf16.h>
#include <cstdint>

// B=16,H=128 -> 2048 groups; per group X[128,256], D=32.
#define NTHR 256

// ---------------- SMEM layout (bytes) ----------------
#define XSTR    544                  // X row stride (272 bf16 slots)
#define XH_OFF  0                    // X hi [128][XSTR]  = 69,632 (read once into regs)
#define XL_OFF  69632                // X lo (A-lo source, read per chunk)
#define WB0     139264               // weight buffer 0 (34,816)
#define WB1     174080               // weight buffer 1 (34,816)
#define WCHUNK  34816                // chunk image: hi[32][XSTR] + lo[32][XSTR]
#define WLO     17408
#define KH_OFF  174080               // K image hi [128][KSTR] (overlays WB1)
#define KL_OFF  186368               // K image lo
#define KSTR    96
#define VTH_OFF 208896               // V^T chunk hi [32][VSTR]
#define VTL_OFF 218112               // V^T chunk lo
#define VSTR    288
#define SMEM_BYTES 227328

// k-permutation: (2q,2q+1,2q+8,2q+9) contiguous per 16-block -> LDS.64 frags
__device__ __forceinline__ int kslot(int k) {
    return (k & ~15) | (((k >> 1) & 3) << 2) | (((k >> 3) & 1) << 1) | (k & 1);
}

// 10 weight-chunk images: 0=Wq, 1=Wk, 2..9=Wv col-chunks of 32
__device__ __align__(16) unsigned char g_wimg[10 * WCHUNK];

__device__ __forceinline__ uint32_t smem_u32(const void* p) {
    uint32_t a;
    asm("{ .reg .u64 t; cvta.to.shared.u64 t, %1; cvt.u32.u64 %0, t; }" : "=r"(a) : "l"(p));
    return a;
}
__device__ __forceinline__ void cp16(void* sdst, const void* gsrc) {
    asm volatile("cp.async.cg.shared.global [%0], [%1], 16;"
                 :: "r"(smem_u32(sdst)), "l"(gsrc));
}
#define CP_COMMIT() asm volatile("cp.async.commit_group;" ::: "memory")
#define CP_WAIT0()  asm volatile("cp.async.wait_group 0;" ::: "memory")

__device__ __forceinline__ void mma16816(float* c, uint32_t a0, uint32_t a1,
                                         uint32_t a2, uint32_t a3,
                                         uint32_t b0, uint32_t b1) {
    asm volatile(
        "mma.sync.aligned.m16n8k16.row.col.f32.bf16.bf16.f32 "
        "{%0,%1,%2,%3},{%4,%5,%6,%7},{%8,%9},{%0,%1,%2,%3};"
        : "+f"(c[0]), "+f"(c[1]), "+f"(c[2]), "+f"(c[3])
        : "r"(a0), "r"(a1), "r"(a2), "r"(a3), "r"(b0), "r"(b1));
}
// 3-pass split with A-hi packed in a uint4 (x,y = a0,a2 row lq; z,w = a1,a3 row lq+8)
__device__ __forceinline__ void mma3r(float* c, uint4 AH, uint2 al0, uint2 al1,
                                      uint2 bh, uint2 bl) {
    mma16816(c, AH.x, AH.z, AH.y, AH.w, bh.x, bh.y);
    mma16816(c, AH.x, AH.z, AH.y, AH.w, bl.x, bl.y);
    mma16816(c, al0.x, al1.x, al0.y, al1.y, bh.x, bh.y);
}
__device__ __forceinline__ uint32_t pack_hi(float x, float y) {
    __nv_bfloat162 p = __floats2bfloat162_rn(x, y);
    return *reinterpret_cast<uint32_t*>(&p);
}
__device__ __forceinline__ uint32_t pack_lo(float x, float y) {
    float xh = __bfloat162float(__float2bfloat16(x));
    float yh = __bfloat162float(__float2bfloat16(y));
    __nv_bfloat162 p = __floats2bfloat162_rn(x - xh, y - yh);
    return *reinterpret_cast<uint32_t*>(&p);
}

// =============== prep: weights -> bf16 hi/lo SMEM-image chunks ===============
__global__ void prep_weights(const float* __restrict__ Wq, const float* __restrict__ Wk,
                             const float* __restrict__ Wv) {
    int idx = blockIdx.x * 256 + threadIdx.x;   // 81920 total
    int chunk = idx >> 13;
    int n = (idx >> 8) & 31;
    int k = idx & 255;
    float w;
    if (chunk == 0)      w = Wq[k * 32 + n];
    else if (chunk == 1) w = Wk[k * 32 + n];
    else                 w = Wv[k * 256 + (chunk - 2) * 32 + n];
    __nv_bfloat16 hh = __float2bfloat16(w);
    __nv_bfloat16 ll = __float2bfloat16(w - __bfloat162float(hh));
    unsigned off = (unsigned)chunk * WCHUNK + (unsigned)n * XSTR + (unsigned)kslot(k) * 2;
    *(__nv_bfloat16*)(g_wimg + off)       = hh;
    *(__nv_bfloat16*)(g_wimg + off + WLO) = ll;
}

// =============== main: one CTA (8 warps) per (b,h) group ===============
__global__ __launch_bounds__(NTHR, 1)
void attn_mma_kernel(const float* __restrict__ X,
                     const float* __restrict__ bq, const float* __restrict__ bk,
                     const float* __restrict__ bv, float* __restrict__ out) {
    extern __shared__ unsigned char sm[];
    const int t = threadIdx.x, w = t >> 5, lane = t & 31;
    const int q = lane & 3, lq = lane >> 2;
    const int R = w * 16;
    const long long g = blockIdx.x;
    const float* Xg = X + g * 32768LL;
    float* Og = out + g * 32768LL;

    // prefetch Wq -> WB0, Wk -> WB1
    for (int i = t; i < WCHUNK / 16; i += NTHR) cp16(sm + WB0 + i * 16, g_wimg + i * 16);
    for (int i = t; i < WCHUNK / 16; i += NTHR) cp16(sm + WB1 + i * 16, g_wimg + WCHUNK + i * 16);
    CP_COMMIT();

    // X load + bf16 hi/lo split into permuted layout
    {
        const float4* X4 = (const float4*)Xg;
        for (int i = t; i < 8192; i += NTHR) {
            int row = i >> 6, k0 = (i & 63) * 4;
            float4 f = X4[i];
            int s0 = kslot(k0), s1 = kslot(k0 + 2);
            unsigned b = (unsigned)row * XSTR;
            *(uint32_t*)(sm + XH_OFF + b + s0 * 2) = pack_hi(f.x, f.y);
            *(uint32_t*)(sm + XH_OFF + b + s1 * 2) = pack_hi(f.z, f.w);
            *(uint32_t*)(sm + XL_OFF + b + s0 * 2) = pack_lo(f.x, f.y);
            *(uint32_t*)(sm + XL_OFF + b + s1 * 2) = pack_lo(f.z, f.w);
        }
    }
    CP_WAIT0();
    __syncthreads();

    const unsigned char* XH0 = sm + XH_OFF + (unsigned)(R + lq) * XSTR;
    const unsigned char* XH1 = XH0 + 8 * XSTR;
    const unsigned char* XL0 = sm + XL_OFF + (unsigned)(R + lq) * XSTR;
    const unsigned char* XL1 = XL0 + 8 * XSTR;

    // ---- one-time: load this warp's A-hi fragments into registers (64 regs) ----
    uint4 Ahi[16];
    #pragma unroll
    for (int kt = 0; kt < 16; kt++) {
        unsigned ko = kt * 32 + q * 8;
        uint2 a0 = *(const uint2*)(XH0 + ko);
        uint2 a1 = *(const uint2*)(XH1 + ko);
        Ahi[kt] = make_uint4(a0.x, a0.y, a1.x, a1.y);
    }

    // ---------------- fused Q + K projection ----------------
    float Cq[4][4], Ck[4][4];
    #pragma unroll
    for (int n = 0; n < 4; n++) {
        Cq[n][0] = Cq[n][1] = Cq[n][2] = Cq[n][3] = 0.f;
        Ck[n][0] = Ck[n][1] = Ck[n][2] = Ck[n][3] = 0.f;
    }
    #pragma unroll 4
    for (int kt = 0; kt < 16; kt++) {
        unsigned ko = kt * 32 + q * 8;
        uint2 al0 = *(const uint2*)(XL0 + ko), al1 = *(const uint2*)(XL1 + ko);
        #pragma unroll
        for (int nt = 0; nt < 4; nt++) {
            const unsigned char* Bq = sm + WB0 + (unsigned)(nt * 8 + lq) * XSTR + ko;
            const unsigned char* Bk = sm + WB1 + (unsigned)(nt * 8 + lq) * XSTR + ko;
            mma3r(Cq[nt], Ahi[kt], al0, al1, *(const uint2*)Bq, *(const uint2*)(Bq + WLO));
            mma3r(Ck[nt], Ahi[kt], al0, al1, *(const uint2*)Bk, *(const uint2*)(Bk + WLO));
        }
    }
    // +bq, repack into scores A-fragments
    uint32_t qh[2][4], ql[2][4];
    #pragma unroll
    for (int nt = 0; nt < 4; nt++) {
        float2 bb = *(const float2*)(bq + nt * 8 + 2 * q);
        Cq[nt][0] += bb.x; Cq[nt][1] += bb.y; Cq[nt][2] += bb.x; Cq[nt][3] += bb.y;
    }
    #pragma unroll
    for (int kt = 0; kt < 2; kt++) {
        qh[kt][0] = pack_hi(Cq[2*kt][0],   Cq[2*kt][1]);
        qh[kt][1] = pack_hi(Cq[2*kt][2],   Cq[2*kt][3]);
        qh[kt][2] = pack_hi(Cq[2*kt+1][0], Cq[2*kt+1][1]);
        qh[kt][3] = pack_hi(Cq[2*kt+1][2], Cq[2*kt+1][3]);
        ql[kt][0] = pack_lo(Cq[2*kt][0],   Cq[2*kt][1]);
        ql[kt][1] = pack_lo(Cq[2*kt][2],   Cq[2*kt][3]);
        ql[kt][2] = pack_lo(Cq[2*kt+1][0], Cq[2*kt+1][1]);
        ql[kt][3] = pack_lo(Cq[2*kt+1][2], Cq[2*kt+1][3]);
    }
    __syncthreads();   // all warps done reading WB0/WB1 as weights

    // prefetch Wv chunk 0 -> WB0 (overlaps K-image write + scores)
    for (int i = t; i < WCHUNK / 16; i += NTHR) cp16(sm + WB0 + i * 16, g_wimg + 2 * WCHUNK + i * 16);
    CP_COMMIT();

    // write K image (+bk) into WB1 region, split hi/lo
    #pragma unroll
    for (int nt = 0; nt < 4; nt++) {
        float2 bb = *(const float2*)(bk + nt * 8 + 2 * q);
        float c0 = Ck[nt][0] + bb.x, c1 = Ck[nt][1] + bb.y;
        float c2 = Ck[nt][2] + bb.x, c3 = Ck[nt][3] + bb.y;
        int p = kslot(nt * 8 + 2 * q) * 2;
        unsigned o0 = (unsigned)(R + lq) * KSTR + p;
        unsigned o1 = (unsigned)(R + lq + 8) * KSTR + p;
        *(uint32_t*)(sm + KH_OFF + o0) = pack_hi(c0, c1);
        *(uint32_t*)(sm + KH_OFF + o1) = pack_hi(c2, c3);
        *(uint32_t*)(sm + KL_OFF + o0) = pack_lo(c0, c1);
        *(uint32_t*)(sm + KL_OFF + o1) = pack_lo(c2, c3);
    }
    __syncthreads();

    // ---------------- scores S = Q @ K^T (nt-groups of 4 for ILP) ----------------
    float Cs[16][4];
    #pragma unroll
    for (int n = 0; n < 16; n++) { Cs[n][0] = Cs[n][1] = Cs[n][2] = Cs[n][3] = 0.f; }
    #pragma unroll
    for (int ng = 0; ng < 4; ng++) {
        #pragma unroll
        for (int kt = 0; kt < 2; kt++) {
            unsigned ko = kt * 32 + q * 8;
            #pragma unroll
            for (int ni = 0; ni < 4; ni++) {
                int nt = ng * 4 + ni;
                const unsigned char* Kp = sm + KH_OFF + (unsigned)(nt * 8 + lq) * KSTR + ko;
                uint2 bh = *(const uint2*)Kp;
                uint2 bl = *(const uint2*)(Kp + (KL_OFF - KH_OFF));
                mma16816(Cs[nt], qh[kt][0], qh[kt][1], qh[kt][2], qh[kt][3], bh.x, bh.y);
                mma16816(Cs[nt], qh[kt][0], qh[kt][1], qh[kt][2], qh[kt][3], bl.x, bl.y);
                mma16816(Cs[nt], ql[kt][0], ql[kt][1], ql[kt][2], ql[kt][3], bh.x, bh.y);
            }
        }
    }

    // ---------------- softmax (registers + quad shuffles) ----------------
    {
        float m0 = -1e30f, m1 = -1e30f;
        #pragma unroll
        for (int nt = 0; nt < 16; nt++) {
            m0 = fmaxf(m0, fmaxf(Cs[nt][0], Cs[nt][1]));
            m1 = fmaxf(m1, fmaxf(Cs[nt][2], Cs[nt][3]));
        }
        m0 = fmaxf(m0, __shfl_xor_sync(0xffffffffu, m0, 1));
        m0 = fmaxf(m0, __shfl_xor_sync(0xffffffffu, m0, 2));
        m1 = fmaxf(m1, __shfl_xor_sync(0xffffffffu, m1, 1));
        m1 = fmaxf(m1, __shfl_xor_sync(0xffffffffu, m1, 2));
        float s0 = 0.f, s1 = 0.f;
        #pragma unroll
        for (int nt = 0; nt < 16; nt++) {
            Cs[nt][0] = __expf(Cs[nt][0] - m0); Cs[nt][1] = __expf(Cs[nt][1] - m0);
            Cs[nt][2] = __expf(Cs[nt][2] - m1); Cs[nt][3] = __expf(Cs[nt][3] - m1);
            s0 += Cs[nt][0] + Cs[nt][1];
            s1 += Cs[nt][2] + Cs[nt][3];
        }
        s0 += __shfl_xor_sync(0xffffffffu, s0, 1);
        s0 += __shfl_xor_sync(0xffffffffu, s0, 2);
        s1 += __shfl_xor_sync(0xffffffffu, s1, 1);
        s1 += __shfl_xor_sync(0xffffffffu, s1, 2);
        const float i0 = 1.f / s0, i1 = 1.f / s1;
        #pragma unroll
        for (int nt = 0; nt < 16; nt++) {
            Cs[nt][0] *= i0; Cs[nt][1] *= i0; Cs[nt][2] *= i1; Cs[nt][3] *= i1;
        }
    }

    // repack attn into A-fragments (hi/lo)
    uint32_t ah[8][4], al[8][4];
    #pragma unroll
    for (int kt = 0; kt < 8; kt++) {
        ah[kt][0] = pack_hi(Cs[2*kt][0],   Cs[2*kt][1]);
        ah[kt][1] = pack_hi(Cs[2*kt][2],   Cs[2*kt][3]);
        ah[kt][2] = pack_hi(Cs[2*kt+1][0], Cs[2*kt+1][1]);
        ah[kt][3] = pack_hi(Cs[2*kt+1][2], Cs[2*kt+1][3]);
        al[kt][0] = pack_lo(Cs[2*kt][0],   Cs[2*kt][1]);
        al[kt][1] = pack_lo(Cs[2*kt][2],   Cs[2*kt][3]);
        al[kt][2] = pack_lo(Cs[2*kt+1][0], Cs[2*kt+1][1]);
        al[kt][3] = pack_lo(Cs[2*kt+1][2], Cs[2*kt+1][3]);
    }

    // precomputed V-transpose constants
    const int j2 = 2 * (lq >> 1);
    const int pA = kslot(R + j2) * 2;        // token pair (R+j2, R+j2+1)
    const int pB = kslot(R + j2 + 8) * 2;    // token pair (R+j2+8, R+j2+9)
    const bool oddlq = (lq & 1);

    // ---------------- 8 output-column chunks of 32 ----------------
    for (int c = 0; c < 8; c++) {
        const unsigned buf = (c & 1) ? WB1 : WB0;
        CP_WAIT0();
        __syncthreads();   // chunk weights ready; prev-iter VT reads done
        if (c < 7) {
            unsigned dst = (c & 1) ? WB0 : WB1;
            const unsigned char* src = g_wimg + (unsigned)(c + 3) * WCHUNK;
            for (int i = t; i < WCHUNK / 16; i += NTHR) cp16(sm + dst + i * 16, src + i * 16);
            CP_COMMIT();
        }

        // V chunk = X @ Wv[:, c*32 .. c*32+31]  (A-hi from registers)
        float Cv[4][4];
        #pragma unroll
        for (int n = 0; n < 4; n++) { Cv[n][0] = Cv[n][1] = Cv[n][2] = Cv[n][3] = 0.f; }
        #pragma unroll 4
        for (int kt = 0; kt < 16; kt++) {
            unsigned ko = kt * 32 + q * 8;
            uint2 al0 = *(const uint2*)(XL0 + ko), al1 = *(const uint2*)(XL1 + ko);
            #pragma unroll
            for (int nt = 0; nt < 4; nt++) {
                const unsigned char* B = sm + buf + (unsigned)(nt * 8 + lq) * XSTR + ko;
                mma3r(Cv[nt], Ahi[kt], al0, al1, *(const uint2*)B, *(const uint2*)(B + WLO));
            }
        }
        // transpose-store V chunk: shfl.xor(4) exchange, pack bf16 pairs -> STS.32
        #pragma unroll
        for (int nt = 0; nt < 4; nt++) {
            float v0 = Cv[nt][0], v1 = Cv[nt][1], v2 = Cv[nt][2], v3 = Cv[nt][3];
            float sendA = oddlq ? v0 : v1;
            float recvA = __shfl_xor_sync(0xffffffffu, sendA, 4);
            float sendB = oddlq ? v2 : v3;
            float recvB = __shfl_xor_sync(0xffffffffu, sendB, 4);
            float a0 = oddlq ? recvA : v0, a1 = oddlq ? v1 : recvA;
            float b0 = oddlq ? recvB : v2, b1 = oddlq ? v3 : recvB;
            unsigned cc = (unsigned)(nt * 8 + 2 * q + (oddlq ? 1 : 0)) * VSTR;
            *(uint32_t*)(sm + VTH_OFF + cc + pA) = pack_hi(a0, a1);
            *(uint32_t*)(sm + VTH_OFF + cc + pB) = pack_hi(b0, b1);
            *(uint32_t*)(sm + VTL_OFF + cc + pA) = pack_lo(a0, a1);
            *(uint32_t*)(sm + VTL_OFF + cc + pB) = pack_lo(b0, b1);
        }
        __syncthreads();

        // O chunk = attn @ V  (kt outer, nt inner -> 4 independent chains)
        float Co[4][4];
        #pragma unroll
        for (int n = 0; n < 4; n++) { Co[n][0] = Co[n][1] = Co[n][2] = Co[n][3] = 0.f; }
        #pragma unroll
        for (int kt = 0; kt < 8; kt++) {
            unsigned ko = kt * 32 + q * 8;
            #pragma unroll
            for (int nt = 0; nt < 4; nt++) {
                const unsigned char* Vp = sm + VTH_OFF + (unsigned)(nt * 8 + lq) * VSTR + ko;
                uint2 bh = *(const uint2*)Vp;
                uint2 bl = *(const uint2*)(Vp + (VTL_OFF - VTH_OFF));
                mma16816(Co[nt], ah[kt][0], ah[kt][1], ah[kt][2], ah[kt][3], bh.x, bh.y);
                mma16816(Co[nt], ah[kt][0], ah[kt][1], ah[kt][2], ah[kt][3], bl.x, bl.y);
                mma16816(Co[nt], al[kt][0], al[kt][1], al[kt][2], al[kt][3], bh.x, bh.y);
            }
        }
        // epilogue: +bv, store (softmax rows sum to 1 -> bias adds directly)
        #pragma unroll
        for (int nt = 0; nt < 4; nt++) {
            int col = c * 32 + nt * 8 + 2 * q;
            float2 bb = *(const float2*)(bv + col);
            float2 o0 = make_float2(Co[nt][0] + bb.x, Co[nt][1] + bb.y);
            float2 o1 = make_float2(Co[nt][2] + bb.x, Co[nt][3] + bb.y);
            *(float2*)(Og + (long long)(R + lq) * 256 + col) = o0;
            *(float2*)(Og + (long long)(R + lq + 8) * 256 + col) = o1;
        }
    }
}

extern "C" void kernel_launch(void* const* d_in, const int* in_sizes, int n_in,
                              void* d_out, int out_size) {
    const float* X  = (const float*)d_in[0];
    const float* Wq = (const float*)d_in[1];
    const float* bq = (const float*)d_in[2];
    const float* Wk = (const float*)d_in[3];
    const float* bk = (const float*)d_in[4];
    const float* Wv = (const float*)d_in[5];
    const float* bv = (const float*)d_in[6];
    float* out = (float*)d_out;

    const int groups = in_sizes[0] / (128 * 256);   // 2048

    prep_weights<<<320, 256>>>(Wq, Wk, Wv);

    cudaFuncSetAttribute(attn_mma_kernel,
                         cudaFuncAttributeMaxDynamicSharedMemorySize, SMEM_BYTES);
    attn_mma_kernel<<<groups, NTHR, SMEM_BYTES>>>(X, bq, bk, bv, out);
}

// round 9
// speedup vs baseline: 2.6654x; 2.6337x over previous
#include <cuda_runtime.h>
#include <cuda_fp16.h>
#include <cstdint>

// B=16,H=128 -> 2048 groups; per group X[128,256], D=32.
#define NTHR 256

// ---------------- SMEM layout (bytes) ----------------
#define XSTR    544                  // X row stride (272 fp16 slots)
#define XP_OFF  0                    // X fp16 [128][XSTR] = 69,632
#define WB0     69632                // weight buffer 0 (17,408)
#define WCHUNK  17408
#define WB1     87040                // weight buffer 1 (17,408)
#define KH_OFF  87040                // K image [128][96] (overlays WB1)
#define KSTR    96
#define VT_OFF  104448               // V^T chunk [32][288]
#define VSTR    288
#define SMEM_BYTES 113664            // -> 2 CTAs/SM

// k-permutation: (2q,2q+1,2q+8,2q+9) contiguous per 16-block -> LDS.64 frags
__device__ __forceinline__ int kslot(int k) {
    return (k & ~15) | (((k >> 1) & 3) << 2) | (((k >> 3) & 1) << 1) | (k & 1);
}

// 10 weight-chunk images: 0=Wq, 1=Wk, 2..9=Wv col-chunks of 32
__device__ __align__(16) unsigned char g_wimg[10 * WCHUNK];

__device__ __forceinline__ uint32_t smem_u32(const void* p) {
    uint32_t a;
    asm("{ .reg .u64 t; cvta.to.shared.u64 t, %1; cvt.u32.u64 %0, t; }" : "=r"(a) : "l"(p));
    return a;
}
__device__ __forceinline__ void cp16(void* sdst, const void* gsrc) {
    asm volatile("cp.async.cg.shared.global [%0], [%1], 16;"
                 :: "r"(smem_u32(sdst)), "l"(gsrc));
}
#define CP_COMMIT() asm volatile("cp.async.commit_group;" ::: "memory")
#define CP_WAIT0()  asm volatile("cp.async.wait_group 0;" ::: "memory")

__device__ __forceinline__ void mma16816(float* c, uint32_t a0, uint32_t a1,
                                         uint32_t a2, uint32_t a3,
                                         uint32_t b0, uint32_t b1) {
    asm volatile(
        "mma.sync.aligned.m16n8k16.row.col.f32.f16.f16.f32 "
        "{%0,%1,%2,%3},{%4,%5,%6,%7},{%8,%9},{%0,%1,%2,%3};"
        : "+f"(c[0]), "+f"(c[1]), "+f"(c[2]), "+f"(c[3])
        : "r"(a0), "r"(a1), "r"(a2), "r"(a3), "r"(b0), "r"(b1));
}
__device__ __forceinline__ uint32_t packh(float x, float y) {
    __half2 p = __floats2half2_rn(x, y);
    return *reinterpret_cast<uint32_t*>(&p);
}

// =============== prep: weights -> fp16 SMEM-image chunks ===============
__global__ void prep_weights(const float* __restrict__ Wq, const float* __restrict__ Wk,
                             const float* __restrict__ Wv) {
    int idx = blockIdx.x * 256 + threadIdx.x;   // 81920 total
    int chunk = idx >> 13;
    int n = (idx >> 8) & 31;
    int k = idx & 255;
    float w;
    if (chunk == 0)      w = Wq[k * 32 + n];
    else if (chunk == 1) w = Wk[k * 32 + n];
    else                 w = Wv[k * 256 + (chunk - 2) * 32 + n];
    unsigned off = (unsigned)chunk * WCHUNK + (unsigned)n * XSTR + (unsigned)kslot(k) * 2;
    *(__half*)(g_wimg + off) = __float2half(w);
}

// =============== main: one CTA (8 warps) per (b,h) group, 2 CTAs/SM ===============
__global__ __launch_bounds__(NTHR, 2)
void attn_mma_kernel(const float* __restrict__ X,
                     const float* __restrict__ bq, const float* __restrict__ bk,
                     const float* __restrict__ bv, float* __restrict__ out) {
    extern __shared__ unsigned char sm[];
    const int t = threadIdx.x, w = t >> 5, lane = t & 31;
    const int q = lane & 3, lq = lane >> 2;
    const int R = w * 16;
    const long long g = blockIdx.x;
    const float* Xg = X + g * 32768LL;
    float* Og = out + g * 32768LL;

    // prefetch Wq -> WB0, Wk -> WB1
    for (int i = t; i < WCHUNK / 16; i += NTHR) cp16(sm + WB0 + i * 16, g_wimg + i * 16);
    for (int i = t; i < WCHUNK / 16; i += NTHR) cp16(sm + WB1 + i * 16, g_wimg + WCHUNK + i * 16);
    CP_COMMIT();

    // X load -> fp16 permuted image
    {
        const float4* X4 = (const float4*)Xg;
        for (int i = t; i < 8192; i += NTHR) {
            int row = i >> 6, k0 = (i & 63) * 4;
            float4 f = X4[i];
            int s0 = kslot(k0), s1 = kslot(k0 + 2);
            unsigned b = (unsigned)row * XSTR;
            *(uint32_t*)(sm + XP_OFF + b + s0 * 2) = packh(f.x, f.y);
            *(uint32_t*)(sm + XP_OFF + b + s1 * 2) = packh(f.z, f.w);
        }
    }
    CP_WAIT0();
    __syncthreads();

    const unsigned char* XP0 = sm + XP_OFF + (unsigned)(R + lq) * XSTR;
    const unsigned char* XP1 = XP0 + 8 * XSTR;

    // ---------------- fused Q + K projection ----------------
    float Cq[4][4], Ck[4][4];
    #pragma unroll
    for (int n = 0; n < 4; n++) {
        Cq[n][0] = Cq[n][1] = Cq[n][2] = Cq[n][3] = 0.f;
        Ck[n][0] = Ck[n][1] = Ck[n][2] = Ck[n][3] = 0.f;
    }
    #pragma unroll 4
    for (int kt = 0; kt < 16; kt++) {
        unsigned ko = kt * 32 + q * 8;
        uint2 a0 = *(const uint2*)(XP0 + ko), a1 = *(const uint2*)(XP1 + ko);
        #pragma unroll
        for (int nt = 0; nt < 4; nt++) {
            uint2 bqf = *(const uint2*)(sm + WB0 + (unsigned)(nt * 8 + lq) * XSTR + ko);
            uint2 bkf = *(const uint2*)(sm + WB1 + (unsigned)(nt * 8 + lq) * XSTR + ko);
            mma16816(Cq[nt], a0.x, a1.x, a0.y, a1.y, bqf.x, bqf.y);
            mma16816(Ck[nt], a0.x, a1.x, a0.y, a1.y, bkf.x, bkf.y);
        }
    }
    // +bq, repack into scores A-fragments
    uint32_t qh[2][4];
    #pragma unroll
    for (int nt = 0; nt < 4; nt++) {
        float2 bb = *(const float2*)(bq + nt * 8 + 2 * q);
        Cq[nt][0] += bb.x; Cq[nt][1] += bb.y; Cq[nt][2] += bb.x; Cq[nt][3] += bb.y;
    }
    #pragma unroll
    for (int kt = 0; kt < 2; kt++) {
        qh[kt][0] = packh(Cq[2*kt][0],   Cq[2*kt][1]);
        qh[kt][1] = packh(Cq[2*kt][2],   Cq[2*kt][3]);
        qh[kt][2] = packh(Cq[2*kt+1][0], Cq[2*kt+1][1]);
        qh[kt][3] = packh(Cq[2*kt+1][2], Cq[2*kt+1][3]);
    }
    __syncthreads();   // all warps done reading WB0/WB1 as weights

    // prefetch Wv chunk 0 -> WB0 (overlaps K-image write + scores)
    for (int i = t; i < WCHUNK / 16; i += NTHR) cp16(sm + WB0 + i * 16, g_wimg + 2 * WCHUNK + i * 16);
    CP_COMMIT();

    // write K image (+bk) into WB1 region
    #pragma unroll
    for (int nt = 0; nt < 4; nt++) {
        float2 bb = *(const float2*)(bk + nt * 8 + 2 * q);
        float c0 = Ck[nt][0] + bb.x, c1 = Ck[nt][1] + bb.y;
        float c2 = Ck[nt][2] + bb.x, c3 = Ck[nt][3] + bb.y;
        int p = kslot(nt * 8 + 2 * q) * 2;
        *(uint32_t*)(sm + KH_OFF + (unsigned)(R + lq) * KSTR + p)     = packh(c0, c1);
        *(uint32_t*)(sm + KH_OFF + (unsigned)(R + lq + 8) * KSTR + p) = packh(c2, c3);
    }
    __syncthreads();

    // ---------------- scores S = Q @ K^T ----------------
    float Cs[16][4];
    #pragma unroll
    for (int n = 0; n < 16; n++) { Cs[n][0] = Cs[n][1] = Cs[n][2] = Cs[n][3] = 0.f; }
    #pragma unroll
    for (int ng = 0; ng < 4; ng++) {
        #pragma unroll
        for (int kt = 0; kt < 2; kt++) {
            unsigned ko = kt * 32 + q * 8;
            #pragma unroll
            for (int ni = 0; ni < 4; ni++) {
                int nt = ng * 4 + ni;
                uint2 bh = *(const uint2*)(sm + KH_OFF + (unsigned)(nt * 8 + lq) * KSTR + ko);
                mma16816(Cs[nt], qh[kt][0], qh[kt][1], qh[kt][2], qh[kt][3], bh.x, bh.y);
            }
        }
    }

    // ---------------- softmax (registers + quad shuffles) ----------------
    {
        float m0 = -1e30f, m1 = -1e30f;
        #pragma unroll
        for (int nt = 0; nt < 16; nt++) {
            m0 = fmaxf(m0, fmaxf(Cs[nt][0], Cs[nt][1]));
            m1 = fmaxf(m1, fmaxf(Cs[nt][2], Cs[nt][3]));
        }
        m0 = fmaxf(m0, __shfl_xor_sync(0xffffffffu, m0, 1));
        m0 = fmaxf(m0, __shfl_xor_sync(0xffffffffu, m0, 2));
        m1 = fmaxf(m1, __shfl_xor_sync(0xffffffffu, m1, 1));
        m1 = fmaxf(m1, __shfl_xor_sync(0xffffffffu, m1, 2));
        float s0 = 0.f, s1 = 0.f;
        #pragma unroll
        for (int nt = 0; nt < 16; nt++) {
            Cs[nt][0] = __expf(Cs[nt][0] - m0); Cs[nt][1] = __expf(Cs[nt][1] - m0);
            Cs[nt][2] = __expf(Cs[nt][2] - m1); Cs[nt][3] = __expf(Cs[nt][3] - m1);
            s0 += Cs[nt][0] + Cs[nt][1];
            s1 += Cs[nt][2] + Cs[nt][3];
        }
        s0 += __shfl_xor_sync(0xffffffffu, s0, 1);
        s0 += __shfl_xor_sync(0xffffffffu, s0, 2);
        s1 += __shfl_xor_sync(0xffffffffu, s1, 1);
        s1 += __shfl_xor_sync(0xffffffffu, s1, 2);
        const float i0 = 1.f / s0, i1 = 1.f / s1;
        #pragma unroll
        for (int nt = 0; nt < 16; nt++) {
            Cs[nt][0] *= i0; Cs[nt][1] *= i0; Cs[nt][2] *= i1; Cs[nt][3] *= i1;
        }
    }

    // repack attn into A-fragments
    uint32_t ah[8][4];
    #pragma unroll
    for (int kt = 0; kt < 8; kt++) {
        ah[kt][0] = packh(Cs[2*kt][0],   Cs[2*kt][1]);
        ah[kt][1] = packh(Cs[2*kt][2],   Cs[2*kt][3]);
        ah[kt][2] = packh(Cs[2*kt+1][0], Cs[2*kt+1][1]);
        ah[kt][3] = packh(Cs[2*kt+1][2], Cs[2*kt+1][3]);
    }

    // V-transpose constants
    const int j2 = 2 * (lq >> 1);
    const int pA = kslot(R + j2) * 2;        // token pair (R+j2, R+j2+1)
    const int pB = kslot(R + j2 + 8) * 2;    // token pair (R+j2+8, R+j2+9)
    const bool oddlq = (lq & 1);

    // ---------------- 8 output-column chunks of 32 ----------------
    for (int c = 0; c < 8; c++) {
        const unsigned buf = (c & 1) ? WB1 : WB0;
        CP_WAIT0();
        __syncthreads();   // chunk weights ready; prev-iter VT reads done
        if (c < 7) {
            unsigned dst = (c & 1) ? WB0 : WB1;
            const unsigned char* src = g_wimg + (unsigned)(c + 3) * WCHUNK;
            for (int i = t; i < WCHUNK / 16; i += NTHR) cp16(sm + dst + i * 16, src + i * 16);
            CP_COMMIT();
        }

        // V chunk = X @ Wv[:, c*32 .. c*32+31]
        float Cv[4][4];
        #pragma unroll
        for (int n = 0; n < 4; n++) { Cv[n][0] = Cv[n][1] = Cv[n][2] = Cv[n][3] = 0.f; }
        #pragma unroll 4
        for (int kt = 0; kt < 16; kt++) {
            unsigned ko = kt * 32 + q * 8;
            uint2 a0 = *(const uint2*)(XP0 + ko), a1 = *(const uint2*)(XP1 + ko);
            #pragma unroll
            for (int nt = 0; nt < 4; nt++) {
                uint2 bf = *(const uint2*)(sm + buf + (unsigned)(nt * 8 + lq) * XSTR + ko);
                mma16816(Cv[nt], a0.x, a1.x, a0.y, a1.y, bf.x, bf.y);
            }
        }
        // transpose-store V chunk: shfl.xor(4) exchange, pack fp16 pairs -> STS.32
        #pragma unroll
        for (int nt = 0; nt < 4; nt++) {
            float v0 = Cv[nt][0], v1 = Cv[nt][1], v2 = Cv[nt][2], v3 = Cv[nt][3];
            float sendA = oddlq ? v0 : v1;
            float recvA = __shfl_xor_sync(0xffffffffu, sendA, 4);
            float sendB = oddlq ? v2 : v3;
            float recvB = __shfl_xor_sync(0xffffffffu, sendB, 4);
            float a0 = oddlq ? recvA : v0, a1 = oddlq ? v1 : recvA;
            float b0 = oddlq ? recvB : v2, b1 = oddlq ? v3 : recvB;
            unsigned cc = (unsigned)(nt * 8 + 2 * q + (oddlq ? 1 : 0)) * VSTR;
            *(uint32_t*)(sm + VT_OFF + cc + pA) = packh(a0, a1);
            *(uint32_t*)(sm + VT_OFF + cc + pB) = packh(b0, b1);
        }
        __syncthreads();

        // O chunk = attn @ V  (kt outer, nt inner)
        float Co[4][4];
        #pragma unroll
        for (int n = 0; n < 4; n++) { Co[n][0] = Co[n][1] = Co[n][2] = Co[n][3] = 0.f; }
        #pragma unroll
        for (int kt = 0; kt < 8; kt++) {
            unsigned ko = kt * 32 + q * 8;
            #pragma unroll
            for (int nt = 0; nt < 4; nt++) {
                uint2 bh = *(const uint2*)(sm + VT_OFF + (unsigned)(nt * 8 + lq) * VSTR + ko);
                mma16816(Co[nt], ah[kt][0], ah[kt][1], ah[kt][2], ah[kt][3], bh.x, bh.y);
            }
        }
        // epilogue: +bv, store (softmax rows sum to 1 -> bias adds directly)
        #pragma unroll
        for (int nt = 0; nt < 4; nt++) {
            int col = c * 32 + nt * 8 + 2 * q;
            float2 bb = *(const float2*)(bv + col);
            float2 o0 = make_float2(Co[nt][0] + bb.x, Co[nt][1] + bb.y);
            float2 o1 = make_float2(Co[nt][2] + bb.x, Co[nt][3] + bb.y);
            *(float2*)(Og + (long long)(R + lq) * 256 + col) = o0;
            *(float2*)(Og + (long long)(R + lq + 8) * 256 + col) = o1;
        }
    }
}

extern "C" void kernel_launch(void* const* d_in, const int* in_sizes, int n_in,
                              void* d_out, int out_size) {
    const float* X  = (const float*)d_in[0];
    const float* Wq = (const float*)d_in[1];
    const float* bq = (const float*)d_in[2];
    const float* Wk = (const float*)d_in[3];
    const float* bk = (const float*)d_in[4];
    const float* Wv = (const float*)d_in[5];
    const float* bv = (const float*)d_in[6];
    float* out = (float*)d_out;

    const int groups = in_sizes[0] / (128 * 256);   // 2048

    prep_weights<<<320, 256>>>(Wq, Wk, Wv);

    cudaFuncSetAttribute(attn_mma_kernel,
                         cudaFuncAttributeMaxDynamicSharedMemorySize, SMEM_BYTES);
    attn_mma_kernel<<<groups, NTHR, SMEM_BYTES>>>(X, bq, bk, bv, out);
}